// round 6
// baseline (speedup 1.0000x reference)
#include <cuda_runtime.h>
#include <cuda_bf16.h>
#include <cstdint>

// Problem constants
#define C_IN   8
#define C_OUT  16
#define N_IN   8192      // C_IN*32*32
#define N_OUT  16384     // C_OUT*32*32
#define ROWS   8193      // N_IN + 1
#define COLS   16385     // N_OUT + 1

#define LOHI_BLOCKS 64
#define NTHREADS    256
#define GRIDN       148          // 1 block per SM (128KB+ dyn smem)
#define BUF_ELEMS   16384        // 64KB per buffer
#define SMEM_BYTES  (2 * BUF_ELEMS * 4)

__device__ __forceinline__ unsigned smem_u32(const void* p) {
    unsigned a;
    asm("{ .reg .u64 t; cvta.to.shared.u64 t, %1; cvt.u32.u64 %0, t; }" : "=r"(a) : "l"(p));
    return a;
}

// Value of M[r, col] for weight row r=(ci,y,x). Handles every column incl. last.
__device__ __forceinline__ float elem_val(unsigned col, unsigned ci, unsigned y,
                                          unsigned x, const float* __restrict__ wgt) {
    if (col >= 16384u) return 0.f;
    const unsigned c  = col >> 10;
    const unsigned i  = (col >> 5) & 31u;
    const unsigned j  = col & 31u;
    const unsigned kh = y - i + 1u;                // valid iff <= 2 (unsigned wrap)
    const unsigned kw = x - j + 1u;
    return (kh <= 2u && kw <= 2u)
        ? __ldg(wgt + ((c * 8u + ci) * 3u + kh) * 3u + kw) : 0.f;
}

__global__ __launch_bounds__(NTHREADS, 1)
void conv_abs_tma_kernel(const float* __restrict__ cl,
                         const float* __restrict__ cu,
                         const float* __restrict__ wgt,
                         const float* __restrict__ bias,
                         float* __restrict__ out)
{
    extern __shared__ float sbuf[];        // [2][BUF_ELEMS]
    __shared__ float s_w[72];
    const int t = threadIdx.x;
    float* __restrict__ M = out + 2 * N_OUT;

    // ---- zero both row-image buffers once ----
    {
        float4* sb4 = reinterpret_cast<float4*>(sbuf);
        const float4 z4 = make_float4(0.f, 0.f, 0.f, 0.f);
        #pragma unroll 8
        for (int k = t; k < 2 * BUF_ELEMS / 4; k += NTHREADS) sb4[k] = z4;
    }

    // ---- lo/hi (blocks 0..63) ----
    if (blockIdx.x < LOHI_BLOCKS) {
        int gid = blockIdx.x * NTHREADS + t;
        int c   = gid >> 10;
        int rem = gid & 1023;
        int i   = rem >> 5;
        int j   = rem & 31;
        if (t < 72) s_w[t] = wgt[c * 72 + t];   // block spans one channel c
        __syncthreads();

        float accL = bias[c];
        float accH = accL;
        #pragma unroll
        for (int ci = 0; ci < C_IN; ci++) {
            #pragma unroll
            for (int kh = 0; kh < 3; kh++) {
                int y = i - 1 + kh;
                if ((unsigned)y >= 32u) continue;
                #pragma unroll
                for (int kw = 0; kw < 3; kw++) {
                    int x = j - 1 + kw;
                    if ((unsigned)x >= 32u) continue;
                    float w   = s_w[(ci * 3 + kh) * 3 + kw];
                    int   tap = ci * 1024 + y * 32 + x;
                    float l = __ldg(cl + tap);
                    float u = __ldg(cu + tap);
                    accL += w * (w > 0.f ? l : u);
                    accH += w * (w > 0.f ? u : l);
                }
            }
        }
        out[gid]         = accL;
        out[N_OUT + gid] = accH;
    } else if (blockIdx.x == LOHI_BLOCKS) {
        // ---- bias row r == 8192 (base 16B-aligned: 8192*16385 % 4 == 0) ----
        float* __restrict__ brow = M + (size_t)8192 * (size_t)COLS;
        #pragma unroll 4
        for (unsigned q = t; q < 4096u; q += NTHREADS) {
            const unsigned col = 4u * q;
            const float b = __ldg(bias + (col >> 10));
            *reinterpret_cast<float4*>(brow + col) = make_float4(b, b, b, b);
        }
        if (t == 0) brow[16384] = 1.0f;
    }
    __syncthreads();   // buffers zeroed + side work done before streaming

    // ---- per-thread tap identity (threads 0..143) ----
    const unsigned tc  = (unsigned)t / 9u;
    const unsigned trm = (unsigned)t - 9u * tc;
    const unsigned tdy = trm / 3u;
    const unsigned tdx = trm - 3u * tdy;

    int last0 = -1, last1 = -1;   // row last imaged in buffer 0 / 1
    int it = 0;

    for (unsigned r = blockIdx.x; r < 8192u; r += GRIDN, ++it) {
        const int bsel = it & 1;
        float* __restrict__ buf = sbuf + bsel * BUF_ELEMS;

        // Recycle: ensure all but the newest bulk group finished READING smem.
        if (t == 0)
            asm volatile("cp.async.bulk.wait_group.read 1;" ::: "memory");
        __syncthreads();

        const unsigned ci = r >> 10;
        const unsigned y  = (r >> 5) & 31u;
        const unsigned x  = r & 31u;
        const unsigned p  = (4u - (r & 3u)) & 3u;                // head peel
        const unsigned bulk_elems = ((16385u - p) >> 2) << 2;    // 16384 or 16380

        if (t < 144) {
            // unpatch the taps of the row previously imaged in this buffer
            const int lr = bsel ? last1 : last0;
            if (lr >= 0) {
                const unsigned oy = ((unsigned)lr >> 5) & 31u;
                const unsigned ox = (unsigned)lr & 31u;
                const unsigned op = (4u - ((unsigned)lr & 3u)) & 3u;
                const unsigned ob = ((16385u - op) >> 2) << 2;
                const int oi = (int)oy - 1 + (int)tdy;
                const int oj = (int)ox - 1 + (int)tdx;
                if ((unsigned)oi < 32u && (unsigned)oj < 32u) {
                    const unsigned ocol = tc * 1024u + (unsigned)oi * 32u + (unsigned)oj;
                    if (ocol >= op && ocol < op + ob) buf[ocol - op] = 0.f;
                }
            }
            // patch this row's taps
            const int i = (int)y - 1 + (int)tdy;
            const int j = (int)x - 1 + (int)tdx;
            if ((unsigned)i < 32u && (unsigned)j < 32u) {
                const unsigned col = tc * 1024u + (unsigned)i * 32u + (unsigned)j;
                if (col >= p && col < p + bulk_elems)
                    buf[col - p] = __ldg(wgt + ((tc * 8u + ci) * 3u + (2u - tdy)) * 3u
                                              + (2u - tdx));
            }
        }

        float* __restrict__ row = M + (size_t)r * (size_t)COLS;

        // head scalars [0, p)
        if (t >= 160 && t < 160 + (int)p) {
            const unsigned col = (unsigned)(t - 160);
            row[col] = elem_val(col, ci, y, x, wgt);
        }
        // tail scalars [p + bulk_elems, 16385)
        {
            const unsigned tail_start = p + bulk_elems;
            const unsigned ntail = (unsigned)COLS - tail_start;   // 0..3
            if (t >= 192 && t < 192 + (int)ntail) {
                const unsigned col = tail_start + (unsigned)(t - 192);
                row[col] = elem_val(col, ci, y, x, wgt);
            }
        }

        __syncthreads();   // patches visible; then one thread launches the bulk store

        if (t == 0) {
            asm volatile("fence.proxy.async.shared::cta;" ::: "memory");
            const unsigned src = smem_u32(buf);
            asm volatile(
                "cp.async.bulk.global.shared::cta.bulk_group [%0], [%1], %2;"
                :: "l"(row + p), "r"(src), "r"(bulk_elems * 4u) : "memory");
            asm volatile("cp.async.bulk.commit_group;" ::: "memory");
        }

        if (bsel) last1 = (int)r; else last0 = (int)r;
    }

    if (t == 0)
        asm volatile("cp.async.bulk.wait_group 0;" ::: "memory");
}

extern "C" void kernel_launch(void* const* d_in, const int* in_sizes, int n_in,
                              void* d_out, int out_size) {
    const float* cl   = (const float*)d_in[0];
    const float* cu   = (const float*)d_in[1];
    const float* wgt  = (const float*)d_in[2];
    const float* bias = (const float*)d_in[3];
    float* out = (float*)d_out;

    static bool attr_set = false;
    if (!attr_set) {
        cudaFuncSetAttribute(conv_abs_tma_kernel,
                             cudaFuncAttributeMaxDynamicSharedMemorySize, SMEM_BYTES);
        attr_set = true;
    }
    conv_abs_tma_kernel<<<GRIDN, NTHREADS, SMEM_BYTES>>>(cl, cu, wgt, bias, out);
}